// round 15
// baseline (speedup 1.0000x reference)
#include <cuda_runtime.h>

#define BATCH 64
#define DFULL 1024
#define DIM   512
#define ODIM  1024

// ---- bilinear GEMM tiling ----
#define MT     128                 // M rows per CTA
#define KC     32                  // K per stage
#define NSTG   16                  // DIM / KC
#define NSLOT  4                   // cp.async ring slots
#define A_FL   (MT * KC)           // 4096 floats (swizzled, no pad)
#define X_FL   (KC * BATCH)        // 2048 floats (paired layout, no pad)
#define SLOT_FL (A_FL + X_FL)      // 6144 floats
#define A_BYTES (A_FL * 4)         // 16384
#define SLOT_BYTES (SLOT_FL * 4)   // 24576
#define SMEM_DYN (NSLOT * SLOT_BYTES)  // 98304 -> 2 CTAs/SM

// -------- scratch (device globals; no allocation allowed) --------
// paired tf32 x for MMA b-frags: xp[e8][b][tau] = {x[8*e8+tau][b], x[8*e8+tau+4][b]}
__device__ float g_xp [DIM * BATCH];
__device__ float g_xT [DIM * BATCH];   // full x, transposed [d][b] (epilogue)
__device__ float g_x2p[DIM * BATCH];
__device__ float g_x2T[DIM * BATCH];
__device__ float g_part[4 * BATCH * DIM];  // per-quarter partial y (no gmem atomics)

// ================= helpers =================
__device__ __forceinline__ unsigned smem_u32(const void* p) {
    unsigned a;
    asm("{ .reg .u64 t; cvta.to.shared.u64 t, %1; cvt.u32.u64 %0, t; }"
        : "=r"(a) : "l"(p));
    return a;
}
__device__ __forceinline__ void cp_async16(unsigned dst, const void* src) {
    asm volatile("cp.async.cg.shared.global [%0], [%1], 16;"
                 :: "r"(dst), "l"(src) : "memory");
}
#define CP_COMMIT() asm volatile("cp.async.commit_group;" ::: "memory")
#define CP_WAIT(N)  asm volatile("cp.async.wait_group %0;" :: "n"(N) : "memory")

// ldmatrix x4: four 8x8 b16 tiles == one m16 tf32 a-frag (rows g/g+8, cols tau/tau+4)
__device__ __forceinline__ void ldsm_x4(unsigned& r0, unsigned& r1,
                                        unsigned& r2, unsigned& r3, unsigned addr) {
    asm volatile("ldmatrix.sync.aligned.m8n8.x4.shared.b16 {%0,%1,%2,%3}, [%4];"
                 : "=r"(r0), "=r"(r1), "=r"(r2), "=r"(r3) : "r"(addr));
}

// m16n8k8 tf32 HMMA, D += A*B (fp32 accumulate)
#define MMA_TF32(c, a0, a1, a2, a3, b0, b1) \
    asm volatile("mma.sync.aligned.m16n8k8.row.col.f32.tf32.tf32.f32 " \
        "{%0,%1,%2,%3}, {%4,%5,%6,%7}, {%8,%9}, {%0,%1,%2,%3};" \
        : "+f"((c)[0]), "+f"((c)[1]), "+f"((c)[2]), "+f"((c)[3]) \
        : "r"(a0), "r"(a1), "r"(a2), "r"(a3), "r"(b0), "r"(b1))

__device__ __forceinline__ float block_sumsq_val(float v, int t) {
    float ss = v;
    #pragma unroll
    for (int o = 16; o > 0; o >>= 1) ss += __shfl_xor_sync(0xffffffffu, ss, o);
    __shared__ float red[8];
    if ((t & 31) == 0) red[t >> 5] = ss;
    __syncthreads();
    float tot = 0.f;
    #pragma unroll
    for (int w = 0; w < 8; w++) tot += red[w];
    return tot;
}
__device__ __forceinline__ float tf32_rn(float v) {
    unsigned r;
    asm("cvt.rna.tf32.f32 %0, %1;" : "=r"(r) : "f"(v));
    return __uint_as_float(r);
}
__device__ __forceinline__ float part4(int b, int j) {
    return g_part[b * DIM + j]
         + g_part[1 * BATCH * DIM + b * DIM + j]
         + g_part[2 * BATCH * DIM + b * DIM + j]
         + g_part[3 * BATCH * DIM + b * DIM + j];
}
// paired-layout index for element (e, b)
__device__ __forceinline__ int xp_idx(int e, int b) {
    return (e >> 3) * (BATCH * 8) + b * 8 + (e & 3) * 2 + ((e >> 2) & 1);
}

// ================= small kernels =================
__global__ void norm_gather_kernel(const float* __restrict__ x,
                                   const int* __restrict__ idx) {
    const int b = blockIdx.x, t = threadIdx.x;
    float ss = 0.f;
    for (int i = t; i < DFULL; i += 256) { float v = x[b * DFULL + i]; ss += v * v; }
    const float inv = rsqrtf(block_sumsq_val(ss, t));
    const int j = blockIdx.y * 256 + t;
    float v = x[b * DFULL + idx[j]] * inv;
    g_xp[xp_idx(j, b)] = tf32_rn(v);
    g_xT[j * BATCH + b] = v;
}

__global__ void rmsnorm_kernel() {
    const int b = blockIdx.x, t = threadIdx.x;
    float ss = 0.f;
    for (int i = t; i < DIM; i += 256) { float v = part4(b, i); ss += v * v; }
    const float inv = rsqrtf(block_sumsq_val(ss, t));
    const int j = blockIdx.y * 256 + t;
    float v = part4(b, j) * inv;
    g_x2p[xp_idx(j, b)] = tf32_rn(v);
    g_x2T[j * BATCH + b] = v;
}

__global__ void out_kernel(const float* __restrict__ W,
                           const float* __restrict__ bias,
                           float* __restrict__ out) {
    const int b = blockIdx.x, t = threadIdx.x;
    const int o = blockIdx.y * 256 + t;
    __shared__ float xrow[DIM];
    for (int j = t; j < DIM; j += 256) xrow[j] = part4(b, j);
    __syncthreads();
    const float4* w4 = reinterpret_cast<const float4*>(W + (size_t)o * DIM);
    float acc = 0.f;
    #pragma unroll 8
    for (int k4 = 0; k4 < DIM / 4; k4++) {
        float4 wv = __ldg(&w4[k4]);
        const float* xr = &xrow[k4 * 4];
        acc += wv.x * xr[0] + wv.y * xr[1] + wv.z * xr[2] + wv.w * xr[3];
    }
    out[b * ODIM + o] = acc + bias[o];
}

// ================= bilinear via mma.sync tf32 =================
// A smem: row r (128B) holds chunks c at swizzled pos c^(r&7). x smem: paired linear.
__device__ __forceinline__ void copy_stage(unsigned sbase, int slot, int kc,
                                           const float* __restrict__ A,
                                           const float* __restrict__ xp, int t) {
    const unsigned sA = sbase + slot * SLOT_BYTES;
    #pragma unroll
    for (int j = 0; j < 4; j++) {                 // 1024 16B chunks of A (128x32 fp32)
        int i = t + j * 256;
        int r = i >> 3, c = i & 7;
        cp_async16(sA + r * 128 + ((c ^ (r & 7)) << 4),
                   A + (size_t)r * DIM + kc * KC + c * 4);
    }
    const unsigned sX = sA + A_BYTES;
    #pragma unroll
    for (int j = 0; j < 2; j++) {                 // 512 chunks of paired x (8 KB)
        int i = t + j * 256;
        cp_async16(sX + i * 16, xp + kc * X_FL + i * 4);
    }
}

// 8 warps: wk = kk-half (0,1), mg = m-group of 64 rows, ng = n-group of 32 cols.
// Each warp: 64m x 32n x 16k per stage -> 16 acc quads, partials merged in epilogue.
__global__ __launch_bounds__(256, 2)
void bilinear_mma_kernel(const float* __restrict__ Bt, int phase) {
    const float* __restrict__ xp = phase ? g_x2p : g_xp;
    const float* __restrict__ xT = phase ? g_x2T : g_xT;

    extern __shared__ float smf[];
    __shared__ float ysum[BATCH];

    const unsigned sbase = smem_u32(smf);
    const int t = threadIdx.x;
    const int w = t >> 5;
    const int wk = w & 1;            // k-half: kk in {2wk, 2wk+1}
    const int mg = (w >> 1) & 1;     // m-group: rows mg*64 ...
    const int ng = w >> 2;           // n-group: cols ng*32 ...
    const int g = (t & 31) >> 2;     // groupID (0..7)
    const int tau = t & 3;           // threadID_in_group
    const int mat = (t & 31) >> 3;   // ldmatrix tile this lane addresses (0..3)
    const int ro = t & 7;            // row within that tile
    const int hi = mat >> 1;         // chunk half selector (cols +4)
    const int mt = blockIdx.x;       // 2048 CTAs
    const int s_out = mt >> 2;
    const int quarter = mt & 3;
    const float* Asrc = Bt + (size_t)mt * MT * DIM;

    // per-lane ldmatrix row byte-offset base (mi16 steps add 16*128)
    const unsigned rowoff0 = (mg * 64 + ((mat & 1) << 3) + ro) * 128;

    if (t < BATCH) ysum[t] = 0.f;

    float acc[4][4][4];
    #pragma unroll
    for (int mi = 0; mi < 4; mi++)
        #pragma unroll
        for (int ni = 0; ni < 4; ni++)
            #pragma unroll
            for (int k = 0; k < 4; k++) acc[mi][ni][k] = 0.f;

    // prologue: fill NSLOT-1 slots
    #pragma unroll
    for (int kc = 0; kc < NSLOT - 1; kc++) {
        copy_stage(sbase, kc, kc, Asrc, xp, t);
        CP_COMMIT();
    }

    int sl = 0;
    for (int kc = 0; kc < NSTG; kc++) {
        if (kc <= NSTG - 3)      { CP_WAIT(2); }
        else if (kc == NSTG - 2) { CP_WAIT(1); }
        else                     { CP_WAIT(0); }
        __syncthreads();

        // prefetch stage kc+3 into the slot freed by compute(kc-1)
        if (kc + NSLOT - 1 < NSTG) {
            int csl = sl + (NSLOT - 1); if (csl >= NSLOT) csl -= NSLOT;
            copy_stage(sbase, csl, kc + NSLOT - 1, Asrc, xp, t);
            CP_COMMIT();
        }

        const unsigned aBase = sbase + sl * SLOT_BYTES;
        const float* sX = smf + sl * SLOT_FL + A_FL;

        #pragma unroll
        for (int kki = 0; kki < 2; kki++) {
            const int kk = 2 * wk + kki;
            const unsigned pos = (unsigned)(((2 * kk + hi) ^ ro) << 4);
            unsigned a[4][4];
            #pragma unroll
            for (int mi = 0; mi < 4; mi++)
                ldsm_x4(a[mi][0], a[mi][1], a[mi][2], a[mi][3],
                        aBase + rowoff0 + mi * (16 * 128) + pos);
            const float2* bp = reinterpret_cast<const float2*>(sX)
                             + kk * (X_FL / 8) + (ng * 32 + g) * 4 + tau;
            float2 bv[4];
            #pragma unroll
            for (int ni = 0; ni < 4; ni++) bv[ni] = bp[ni * 32];
            #pragma unroll
            for (int ni = 0; ni < 4; ni++) {
                unsigned b0 = __float_as_uint(bv[ni].x);
                unsigned b1 = __float_as_uint(bv[ni].y);
                #pragma unroll
                for (int mi = 0; mi < 4; mi++)
                    MMA_TF32(acc[mi][ni], a[mi][0], a[mi][1], a[mi][2], a[mi][3],
                             b0, b1);
            }
        }
        sl = (sl == NSLOT - 1) ? 0 : sl + 1;
    }

    // ---- epilogue: y[b] += sum_d H[d,b] * x[d,b] (k-half partials merge here) ----
    float s0[4], s1[4];
    #pragma unroll
    for (int ni = 0; ni < 4; ni++) { s0[ni] = 0.f; s1[ni] = 0.f; }

    #pragma unroll
    for (int mi = 0; mi < 4; mi++) {
        const int d0 = quarter * MT + mg * 64 + mi * 16 + g;
        #pragma unroll
        for (int ni = 0; ni < 4; ni++) {
            const int col = ng * 32 + ni * 8 + 2 * tau;
            float2 xa = *reinterpret_cast<const float2*>(xT + d0 * BATCH + col);
            float2 xb = *reinterpret_cast<const float2*>(xT + (d0 + 8) * BATCH + col);
            s0[ni] += acc[mi][ni][0] * xa.x + acc[mi][ni][2] * xb.x;
            s1[ni] += acc[mi][ni][1] * xa.y + acc[mi][ni][3] * xb.y;
        }
    }
    // reduce over groupID lanes (stride-4 butterflies)
    #pragma unroll
    for (int o = 4; o <= 16; o <<= 1) {
        #pragma unroll
        for (int ni = 0; ni < 4; ni++) {
            s0[ni] += __shfl_xor_sync(0xffffffffu, s0[ni], o);
            s1[ni] += __shfl_xor_sync(0xffffffffu, s1[ni], o);
        }
    }
    if (g == 0) {
        #pragma unroll
        for (int ni = 0; ni < 4; ni++) {
            atomicAdd(&ysum[ng * 32 + ni * 8 + 2 * tau],     s0[ni]);
            atomicAdd(&ysum[ng * 32 + ni * 8 + 2 * tau + 1], s1[ni]);
        }
    }
    __syncthreads();
    if (t < BATCH)
        g_part[quarter * BATCH * DIM + t * DIM + s_out] = ysum[t];
}

// ================= launch =================
extern "C" void kernel_launch(void* const* d_in, const int* in_sizes, int n_in,
                              void* d_out, int out_size) {
    (void)out_size;
    const float *x = nullptr, *B1 = nullptr, *B2 = nullptr, *W = nullptr, *bias = nullptr;
    const int* idx = nullptr;
    for (int i = 0; i < n_in; i++) {
        switch (in_sizes[i]) {
            case BATCH * DFULL:  x = (const float*)d_in[i]; break;
            case 134217728:      if (!B1) B1 = (const float*)d_in[i];
                                 else     B2 = (const float*)d_in[i]; break;
            case ODIM * DIM:     W = (const float*)d_in[i]; break;
            case ODIM:           bias = (const float*)d_in[i]; break;
            case DIM:            idx = (const int*)d_in[i]; break;
            default: break;
        }
    }
    float* out = (float*)d_out;

    cudaFuncSetAttribute(bilinear_mma_kernel,
                         cudaFuncAttributeMaxDynamicSharedMemorySize, SMEM_DYN);

    norm_gather_kernel<<<dim3(BATCH, 2), 256>>>(x, idx);
    bilinear_mma_kernel<<<(DIM * DIM) / MT, 256, SMEM_DYN>>>(B1, 0);
    rmsnorm_kernel<<<dim3(BATCH, 2), 256>>>();
    bilinear_mma_kernel<<<(DIM * DIM) / MT, 256, SMEM_DYN>>>(B2, 1);
    out_kernel<<<dim3(BATCH, ODIM / 256), 256>>>(W, bias, out);
}

// round 16
// speedup vs baseline: 1.0569x; 1.0569x over previous
#include <cuda_runtime.h>

#define BATCH 64
#define DFULL 1024
#define DIM   512
#define ODIM  1024

// ---- bilinear GEMM tiling (R14 frame: 3 CTAs/SM, 32x32x32 warp bricks) ----
#define MT     128                 // M rows per CTA
#define KC     32                  // K per stage
#define NSTG   16                  // DIM / KC
#define NSLOT  3                   // cp.async ring slots
#define A_FL   (MT * KC)           // 4096 floats (swizzled, no pad)
#define X_FL   (KC * BATCH)        // 2048 floats (float4-paired layout, no pad)
#define SLOT_FL (A_FL + X_FL)      // 6144 floats
#define A_BYTES (A_FL * 4)         // 16384
#define SLOT_BYTES (SLOT_FL * 4)   // 24576
#define SMEM_DYN (NSLOT * SLOT_BYTES)  // 73728 -> 3 CTAs/SM

// -------- scratch (device globals; no allocation allowed) --------
// float4-paired tf32 x for MMA b-frags:
//   float4 at [e8][b>>4][b&7][e&3] = {x[8e8+t][c], x[8e8+t+4][c], x[8e8+t][c+8], x[8e8+t+4][c+8]}
__device__ float g_xq [DIM * BATCH];
__device__ float g_xT [DIM * BATCH];   // full x, transposed [d][b] (epilogue)
__device__ float g_x2q[DIM * BATCH];
__device__ float g_x2T[DIM * BATCH];
__device__ float g_part[4 * BATCH * DIM];  // per-quarter partial y (no gmem atomics)

// ================= helpers =================
__device__ __forceinline__ unsigned smem_u32(const void* p) {
    unsigned a;
    asm("{ .reg .u64 t; cvta.to.shared.u64 t, %1; cvt.u32.u64 %0, t; }"
        : "=r"(a) : "l"(p));
    return a;
}
__device__ __forceinline__ void cp_async16(unsigned dst, const void* src) {
    asm volatile("cp.async.cg.shared.global [%0], [%1], 16;"
                 :: "r"(dst), "l"(src) : "memory");
}
#define CP_COMMIT() asm volatile("cp.async.commit_group;" ::: "memory")
#define CP_WAIT(N)  asm volatile("cp.async.wait_group %0;" :: "n"(N) : "memory")

// ldmatrix x4: four 8x8 b16 tiles == one m16 tf32 a-frag pair
__device__ __forceinline__ void ldsm_x4(unsigned& r0, unsigned& r1,
                                        unsigned& r2, unsigned& r3, unsigned addr) {
    asm volatile("ldmatrix.sync.aligned.m8n8.x4.shared.b16 {%0,%1,%2,%3}, [%4];"
                 : "=r"(r0), "=r"(r1), "=r"(r2), "=r"(r3) : "r"(addr));
}

// m16n8k8 tf32 HMMA, D += A*B (fp32 accumulate)
#define MMA_TF32(c, a0, a1, a2, a3, b0, b1) \
    asm volatile("mma.sync.aligned.m16n8k8.row.col.f32.tf32.tf32.f32 " \
        "{%0,%1,%2,%3}, {%4,%5,%6,%7}, {%8,%9}, {%0,%1,%2,%3};" \
        : "+f"((c)[0]), "+f"((c)[1]), "+f"((c)[2]), "+f"((c)[3]) \
        : "r"(a0), "r"(a1), "r"(a2), "r"(a3), "r"(b0), "r"(b1))

__device__ __forceinline__ float block_sumsq_val(float v, int t) {
    float ss = v;
    #pragma unroll
    for (int o = 16; o > 0; o >>= 1) ss += __shfl_xor_sync(0xffffffffu, ss, o);
    __shared__ float red[8];
    if ((t & 31) == 0) red[t >> 5] = ss;
    __syncthreads();
    float tot = 0.f;
    #pragma unroll
    for (int w = 0; w < 8; w++) tot += red[w];
    return tot;
}
__device__ __forceinline__ float tf32_rn(float v) {
    unsigned r;
    asm("cvt.rna.tf32.f32 %0, %1;" : "=r"(r) : "f"(v));
    return __uint_as_float(r);
}
__device__ __forceinline__ float part4(int b, int j) {
    return g_part[b * DIM + j]
         + g_part[1 * BATCH * DIM + b * DIM + j]
         + g_part[2 * BATCH * DIM + b * DIM + j]
         + g_part[3 * BATCH * DIM + b * DIM + j];
}
// float4-paired layout: float index for element (e, b)
__device__ __forceinline__ int xq_idx(int e, int b) {
    int f4 = (e >> 3) * 128 + (b >> 4) * 32 + (b & 7) * 4 + (e & 3);
    return f4 * 4 + ((e >> 2) & 1) + 2 * ((b >> 3) & 1);
}

// ================= small kernels =================
__global__ void norm_gather_kernel(const float* __restrict__ x,
                                   const int* __restrict__ idx) {
    const int b = blockIdx.x, t = threadIdx.x;
    float ss = 0.f;
    for (int i = t; i < DFULL; i += 256) { float v = x[b * DFULL + i]; ss += v * v; }
    const float inv = rsqrtf(block_sumsq_val(ss, t));
    const int j = blockIdx.y * 256 + t;
    float v = x[b * DFULL + idx[j]] * inv;
    g_xq[xq_idx(j, b)] = tf32_rn(v);
    g_xT[j * BATCH + b] = v;
}

__global__ void rmsnorm_kernel() {
    const int b = blockIdx.x, t = threadIdx.x;
    float ss = 0.f;
    for (int i = t; i < DIM; i += 256) { float v = part4(b, i); ss += v * v; }
    const float inv = rsqrtf(block_sumsq_val(ss, t));
    const int j = blockIdx.y * 256 + t;
    float v = part4(b, j) * inv;
    g_x2q[xq_idx(j, b)] = tf32_rn(v);
    g_x2T[j * BATCH + b] = v;
}

__global__ void out_kernel(const float* __restrict__ W,
                           const float* __restrict__ bias,
                           float* __restrict__ out) {
    const int b = blockIdx.x, t = threadIdx.x;
    const int o = blockIdx.y * 256 + t;
    __shared__ float xrow[DIM];
    for (int j = t; j < DIM; j += 256) xrow[j] = part4(b, j);
    __syncthreads();
    const float4* w4 = reinterpret_cast<const float4*>(W + (size_t)o * DIM);
    float acc = 0.f;
    #pragma unroll 8
    for (int k4 = 0; k4 < DIM / 4; k4++) {
        float4 wv = __ldg(&w4[k4]);
        const float* xr = &xrow[k4 * 4];
        acc += wv.x * xr[0] + wv.y * xr[1] + wv.z * xr[2] + wv.w * xr[3];
    }
    out[b * ODIM + o] = acc + bias[o];
}

// ================= bilinear via mma.sync tf32 =================
// A smem: row r (128B) holds chunks c at swizzled pos c^(r&7). x smem: float4-paired.
__device__ __forceinline__ void copy_stage(unsigned sbase, int slot, int kc,
                                           const float* __restrict__ A,
                                           const float* __restrict__ xq, int t) {
    const unsigned sA = sbase + slot * SLOT_BYTES;
    #pragma unroll
    for (int j = 0; j < 4; j++) {                 // 1024 16B chunks of A (128x32 fp32)
        int i = t + j * 256;
        int r = i >> 3, c = i & 7;
        cp_async16(sA + r * 128 + ((c ^ (r & 7)) << 4),
                   A + (size_t)r * DIM + kc * KC + c * 4);
    }
    const unsigned sX = sA + A_BYTES;
    #pragma unroll
    for (int j = 0; j < 2; j++) {                 // 512 chunks of paired x (8 KB)
        int i = t + j * 256;
        cp_async16(sX + i * 16, xq + kc * X_FL + i * 4);
    }
}

__global__ __launch_bounds__(256, 3)
void bilinear_mma_kernel(const float* __restrict__ Bt, int phase) {
    const float* __restrict__ xq = phase ? g_x2q : g_xq;
    const float* __restrict__ xT = phase ? g_x2T : g_xT;

    extern __shared__ float smf[];
    __shared__ float ysum[BATCH];

    const unsigned sbase = smem_u32(smf);
    const int t = threadIdx.x;
    const int w = t >> 5;
    const int mg = w & 3;            // m-group: rows mg*32 + mi*16 + ...
    const int ng = w >> 2;           // n-group: cols ng*32 + ...
    const int g = (t & 31) >> 2;     // groupID (0..7)
    const int tau = t & 3;           // threadID_in_group
    const int mat = (t & 31) >> 3;   // ldmatrix tile this lane addresses (0..3)
    const int ro = t & 7;            // row within that tile
    const int hi = mat >> 1;         // chunk half selector (cols +4)
    const int mt = blockIdx.x;       // 2048 CTAs
    const int s_out = mt >> 2;
    const int quarter = mt & 3;
    const float* Asrc = Bt + (size_t)mt * MT * DIM;

    // per-lane ldmatrix row byte-offsets (within a slot's A tile)
    const unsigned rowoff0 = (mg * 32 + ((mat & 1) << 3) + ro) * 128;   // mi=0
    const unsigned rowoff1 = rowoff0 + 16 * 128;                        // mi=1
    // per-lane x float4 offset within a stage's x tile
    const int xoff = (ng * 2) * 32 + g * 4 + tau;

    if (t < BATCH) ysum[t] = 0.f;

    float acc[2][4][4];
    #pragma unroll
    for (int mi = 0; mi < 2; mi++)
        #pragma unroll
        for (int ni = 0; ni < 4; ni++)
            #pragma unroll
            for (int k = 0; k < 4; k++) acc[mi][ni][k] = 0.f;

    // prologue: fill NSLOT-1 slots
    #pragma unroll
    for (int kc = 0; kc < NSLOT - 1; kc++) {
        copy_stage(sbase, kc, kc, Asrc, xq, t);
        CP_COMMIT();
    }

    int sl = 0;
    for (int kc = 0; kc < NSTG; kc++) {
        if (kc < NSTG - 1) { CP_WAIT(1); } else { CP_WAIT(0); }
        __syncthreads();

        // prefetch stage kc+2 into the slot freed by compute(kc-1)
        if (kc + NSLOT - 1 < NSTG) {
            int csl = sl + (NSLOT - 1); if (csl >= NSLOT) csl -= NSLOT;
            copy_stage(sbase, csl, kc + NSLOT - 1, Asrc, xq, t);
            CP_COMMIT();
        }

        const unsigned aBase = sbase + sl * SLOT_BYTES;
        const float4* sXq = reinterpret_cast<const float4*>(smf + sl * SLOT_FL + A_FL);

        #pragma unroll
        for (int kk = 0; kk < 4; kk++) {
            const unsigned pos = (unsigned)(((2 * kk + hi) ^ ro) << 4);
            unsigned a0[4], a1[4];
            ldsm_x4(a0[0], a0[1], a0[2], a0[3], aBase + rowoff0 + pos);
            ldsm_x4(a1[0], a1[1], a1[2], a1[3], aBase + rowoff1 + pos);
            // two LDS.128: b-frags for ni pairs (0,1) and (2,3)
            float4 bv0 = sXq[kk * 128 + xoff];
            float4 bv1 = sXq[kk * 128 + xoff + 32];
            unsigned b00 = __float_as_uint(bv0.x), b01 = __float_as_uint(bv0.y);
            unsigned b10 = __float_as_uint(bv0.z), b11 = __float_as_uint(bv0.w);
            unsigned b20 = __float_as_uint(bv1.x), b21 = __float_as_uint(bv1.y);
            unsigned b30 = __float_as_uint(bv1.z), b31 = __float_as_uint(bv1.w);
            MMA_TF32(acc[0][0], a0[0], a0[1], a0[2], a0[3], b00, b01);
            MMA_TF32(acc[1][0], a1[0], a1[1], a1[2], a1[3], b00, b01);
            MMA_TF32(acc[0][1], a0[0], a0[1], a0[2], a0[3], b10, b11);
            MMA_TF32(acc[1][1], a1[0], a1[1], a1[2], a1[3], b10, b11);
            MMA_TF32(acc[0][2], a0[0], a0[1], a0[2], a0[3], b20, b21);
            MMA_TF32(acc[1][2], a1[0], a1[1], a1[2], a1[3], b20, b21);
            MMA_TF32(acc[0][3], a0[0], a0[1], a0[2], a0[3], b30, b31);
            MMA_TF32(acc[1][3], a1[0], a1[1], a1[2], a1[3], b30, b31);
        }
        sl = (sl == NSLOT - 1) ? 0 : sl + 1;
    }

    // ---- epilogue: y[b] += sum_d H[d,b] * x[d,b] ----
    float s0[4], s1[4];
    #pragma unroll
    for (int ni = 0; ni < 4; ni++) { s0[ni] = 0.f; s1[ni] = 0.f; }

    #pragma unroll
    for (int mi = 0; mi < 2; mi++) {
        const int d0 = quarter * MT + mg * 32 + mi * 16 + g;
        #pragma unroll
        for (int ni = 0; ni < 4; ni++) {
            const int col = ng * 32 + ni * 8 + 2 * tau;
            float2 xa = *reinterpret_cast<const float2*>(xT + d0 * BATCH + col);
            float2 xb = *reinterpret_cast<const float2*>(xT + (d0 + 8) * BATCH + col);
            s0[ni] += acc[mi][ni][0] * xa.x + acc[mi][ni][2] * xb.x;
            s1[ni] += acc[mi][ni][1] * xa.y + acc[mi][ni][3] * xb.y;
        }
    }
    // reduce over groupID lanes (stride-4 butterflies)
    #pragma unroll
    for (int o = 4; o <= 16; o <<= 1) {
        #pragma unroll
        for (int ni = 0; ni < 4; ni++) {
            s0[ni] += __shfl_xor_sync(0xffffffffu, s0[ni], o);
            s1[ni] += __shfl_xor_sync(0xffffffffu, s1[ni], o);
        }
    }
    if (g == 0) {
        #pragma unroll
        for (int ni = 0; ni < 4; ni++) {
            atomicAdd(&ysum[ng * 32 + ni * 8 + 2 * tau],     s0[ni]);
            atomicAdd(&ysum[ng * 32 + ni * 8 + 2 * tau + 1], s1[ni]);
        }
    }
    __syncthreads();
    if (t < BATCH)
        g_part[quarter * BATCH * DIM + t * DIM + s_out] = ysum[t];
}

// ================= launch =================
extern "C" void kernel_launch(void* const* d_in, const int* in_sizes, int n_in,
                              void* d_out, int out_size) {
    (void)out_size;
    const float *x = nullptr, *B1 = nullptr, *B2 = nullptr, *W = nullptr, *bias = nullptr;
    const int* idx = nullptr;
    for (int i = 0; i < n_in; i++) {
        switch (in_sizes[i]) {
            case BATCH * DFULL:  x = (const float*)d_in[i]; break;
            case 134217728:      if (!B1) B1 = (const float*)d_in[i];
                                 else     B2 = (const float*)d_in[i]; break;
            case ODIM * DIM:     W = (const float*)d_in[i]; break;
            case ODIM:           bias = (const float*)d_in[i]; break;
            case DIM:            idx = (const int*)d_in[i]; break;
            default: break;
        }
    }
    float* out = (float*)d_out;

    cudaFuncSetAttribute(bilinear_mma_kernel,
                         cudaFuncAttributeMaxDynamicSharedMemorySize, SMEM_DYN);

    norm_gather_kernel<<<dim3(BATCH, 2), 256>>>(x, idx);
    bilinear_mma_kernel<<<(DIM * DIM) / MT, 256, SMEM_DYN>>>(B1, 0);
    rmsnorm_kernel<<<dim3(BATCH, 2), 256>>>();
    bilinear_mma_kernel<<<(DIM * DIM) / MT, 256, SMEM_DYN>>>(B2, 1);
    out_kernel<<<dim3(BATCH, ODIM / 256), 256>>>(W, bias, out);
}